// round 4
// baseline (speedup 1.0000x reference)
#include <cuda_runtime.h>

// 7-DOF forward kinematics, two propagated 3-vectors, MUFU sincos.
// R4: R3's smem-staged vectorized I/O with the vector-flush indexing fixed.

#define DEG 0.017453292519943295f

__global__ void __launch_bounds__(256) fk_kernel(
    const float* __restrict__ thetas,   // [B, 7]
    float* __restrict__ out,            // [B*3 points][B*3 vectors]
    int n)
{
    __shared__ float s_in[256 * 7];     // 7168 B
    __shared__ float s_out[256 * 6];    // 6144 B: [0,768) pts, [768,1536) vecs

    int tid = threadIdx.x;
    long long ebase = (long long)blockIdx.x * 256;   // first element of block
    bool fast = ((n & 3) == 0) && (ebase + 256 <= n);

    float th0, th1, th2, th3, th4, th5, th6;

    if (fast) {
        // Coalesced 128-bit staging: 448 float4 = 1792 floats
        const float4* g4 = (const float4*)(thetas + ebase * 7);
        float4* s4 = (float4*)s_in;
        s4[tid] = g4[tid];
        if (tid < 192) s4[tid + 256] = g4[tid + 256];
        __syncthreads();
        const float* t = s_in + tid * 7;   // stride 7: bank-conflict-free
        th0 = t[0]; th1 = t[1]; th2 = t[2]; th3 = t[3];
        th4 = t[4]; th5 = t[5]; th6 = t[6];
    } else {
        long long i = ebase + tid;
        if (i >= n) return;
        const float* t = thetas + i * 7;
        th0 = t[0]; th1 = t[1]; th2 = t[2]; th3 = t[3];
        th4 = t[4]; th5 = t[5]; th6 = t[6];
    }

    // Angles in radians (all within __sincosf accurate region)
    float r0 = th0 * DEG;
    float r1 = th1 * DEG;
    float r2 = th2 * DEG;
    float r3 = th3 * DEG;
    float r4 = th4 * (-0.5f * DEG);
    float r5 = fmaf(th5, DEG / 4.5f, 10.0f * DEG);
    float r6 = fmaf(th6, DEG / 4.5f, 60.0f * DEG);

    float s0, c0, s1, c1, s2, c2, s3, c3, s4, c4, s5, c5, s6, c6;
    __sincosf(r0, &s0, &c0);
    __sincosf(r1, &s1, &c1);
    __sincosf(r2, &s2, &c2);
    __sincosf(r3, &s3, &c3);
    __sincosf(r4, &s4, &c4);
    __sincosf(r5, &s5, &c5);
    __sincosf(r6, &s6, &c6);

    float px = 0.f, py = 0.f, pz = 0.f;
    float vx = 0.f, vy = 0.f, vz = 1.f;

#define ROT_Z(c, s) do { \
        float _x = px, _y = py; px = (c)*_x - (s)*_y; py = (s)*_x + (c)*_y; \
        float _a = vx, _b = vy; vx = (c)*_a - (s)*_b; vy = (s)*_a + (c)*_b; \
    } while (0)
#define RY90() do { \
        float _x = px; px = pz; pz = -_x; \
        float _a = vx; vx = vz; vz = -_a; \
    } while (0)
#define RX90() do { \
        float _y = py; py = -pz; pz = _y; \
        float _b = vy; vy = -vz; vz = _b; \
    } while (0)
#define RXM90() do { \
        float _y = py; py = pz; pz = -_y; \
        float _b = vy; vy = vz; vz = -_b; \
    } while (0)

    // Chain right-to-left (T25 first); constant Rz's folded into (c,s) roles
    RY90();                                   // T25: Ry(90)
    px += 6.0f;                               // T24
    ROT_Z(c6, s6);                            // T23: Rz(a6)
    px += 6.0f; py += -1.0f;                  // T22,T21
    ROT_Z(s5, -c5);                           // T20,T19: Rz(a5-90)
    RXM90();                                  // T18
    pz += 10.0f;                              // T17
    ROT_Z(c4, s4);                            // T16: Rz(-th4/2)
    RY90();                                   // T15
    px += 10.0f;                              // T14
    ROT_Z(-c3, s3);                           // T13,T12: Rz(180-th3)
    RX90();                                   // T11
    px += 17.5f;                              // T10
    ROT_Z(c2, -s2);                           // T9: Rz(-th2)
    RXM90();                                  // T8
    px += 3.0f; pz += 9.5f;                   // T7
    ROT_Z(c1, s1);                            // T6
    RY90();                                   // T5
    py += -1.5f; pz += 2.5f;                  // T4
    ROT_Z(-s0, c0);                           // T3,T2: Rz(th0+90)
    py += 5.0f; pz += 19.5f;                  // T1

    if (fast) {
        __syncthreads();   // s_in reads done before smem writes
        float* sp = s_out + tid * 3;          // stride 3: conflict-free
        sp[0] = px; sp[1] = py; sp[2] = pz;
        float* sv = s_out + 768 + tid * 3;
        sv[0] = vx; sv[1] = vy; sv[2] = vz;
        __syncthreads();

        // Flush all 384 float4: so4[0..191] -> points, so4[192..383] -> vectors
        float4* gp = (float4*)(out + ebase * 3);
        float4* gv = (float4*)(out + (long long)n * 3 + ebase * 3);
        const float4* so4 = (const float4*)s_out;
        #pragma unroll
        for (int j = tid; j < 384; j += 256) {
            if (j < 192) gp[j] = so4[j];
            else         gv[j - 192] = so4[j];
        }
    } else {
        long long i = ebase + tid;
        long long base = i * 3;
        out[base + 0] = px;
        out[base + 1] = py;
        out[base + 2] = pz;
        long long vbase = (long long)n * 3 + base;
        out[vbase + 0] = vx;
        out[vbase + 1] = vy;
        out[vbase + 2] = vz;
    }
}

extern "C" void kernel_launch(void* const* d_in, const int* in_sizes, int n_in,
                              void* d_out, int out_size)
{
    const float* thetas = (const float*)d_in[0];
    float* out = (float*)d_out;
    int n = in_sizes[0] / 7;   // B
    int threads = 256;
    int blocks = (n + threads - 1) / threads;
    fk_kernel<<<blocks, threads>>>(thetas, out, n);
}